// round 2
// baseline (speedup 1.0000x reference)
#include <cuda_runtime.h>
#include <math.h>

// Problem constants
#define BATCH   2
#define LSEQ    4096
#define DIMSZ   512
#define NHEADS  8
#define HD      64
#define KSZ     33
#define MROWS   (BATCH * LSEQ)        // 8192
#define QKVDIM  (3 * DIMSZ)           // 1536
#define BQ      128                   // queries per attention block
#define PITCH   161                   // smem pitch for K/V tiles (odd -> conflict free)
#define NKMAX   160

// Scratch (device globals: no allocation allowed)
__device__ float g_qkv[(size_t)MROWS * QKVDIM];   // ~50.3 MB
__device__ float g_att[(size_t)MROWS * DIMSZ];    // ~16.8 MB

// ----------------------------------------------------------------------------
// GEMM (NT): C[M,N] = A[M,K] @ B[N,K]^T + bias[N]
// BM=BN=128, BK=16, 256 threads, 8x8 per-thread micro-tile. M,N,K divisible.
// ----------------------------------------------------------------------------
__global__ void __launch_bounds__(256) gemm_nt_bias(
    const float* __restrict__ A, const float* __restrict__ B,
    const float* __restrict__ bias, float* __restrict__ C,
    int N, int K)
{
    __shared__ float As[16][128];
    __shared__ float Bs[16][128];

    const int tid = threadIdx.x;
    const int m0 = blockIdx.y * 128;
    const int n0 = blockIdx.x * 128;
    const int tm = tid >> 4;    // 0..15
    const int tn = tid & 15;    // 0..15

    float acc[8][8];
#pragma unroll
    for (int i = 0; i < 8; i++)
#pragma unroll
        for (int j = 0; j < 8; j++) acc[i][j] = 0.0f;

    const float* Ag = A + (size_t)m0 * K;
    const float* Bg = B + (size_t)n0 * K;

    for (int k0 = 0; k0 < K; k0 += 16) {
        // Stage tiles: 128 rows x 16 k each = 512 float4 per operand
#pragma unroll
        for (int u = 0; u < 2; u++) {
            int i4  = tid + u * 256;   // 0..511
            int row = i4 >> 2;
            int c4  = i4 & 3;
            float4 av = *(const float4*)(Ag + (size_t)row * K + k0 + c4 * 4);
            As[c4 * 4 + 0][row] = av.x;
            As[c4 * 4 + 1][row] = av.y;
            As[c4 * 4 + 2][row] = av.z;
            As[c4 * 4 + 3][row] = av.w;
            float4 bv = *(const float4*)(Bg + (size_t)row * K + k0 + c4 * 4);
            Bs[c4 * 4 + 0][row] = bv.x;
            Bs[c4 * 4 + 1][row] = bv.y;
            Bs[c4 * 4 + 2][row] = bv.z;
            Bs[c4 * 4 + 3][row] = bv.w;
        }
        __syncthreads();

#pragma unroll
        for (int kk = 0; kk < 16; kk++) {
            float a[8], b[8];
            *(float4*)&a[0] = *(const float4*)&As[kk][tm * 8];
            *(float4*)&a[4] = *(const float4*)&As[kk][tm * 8 + 4];
            *(float4*)&b[0] = *(const float4*)&Bs[kk][tn * 8];
            *(float4*)&b[4] = *(const float4*)&Bs[kk][tn * 8 + 4];
#pragma unroll
            for (int i = 0; i < 8; i++)
#pragma unroll
                for (int j = 0; j < 8; j++)
                    acc[i][j] = fmaf(a[i], b[j], acc[i][j]);
        }
        __syncthreads();
    }

    // Epilogue: bias + store
    float bv[8];
#pragma unroll
    for (int j = 0; j < 8; j++) bv[j] = bias[n0 + tn * 8 + j];

#pragma unroll
    for (int i = 0; i < 8; i++) {
        float4 o0, o1;
        o0.x = acc[i][0] + bv[0];
        o0.y = acc[i][1] + bv[1];
        o0.z = acc[i][2] + bv[2];
        o0.w = acc[i][3] + bv[3];
        o1.x = acc[i][4] + bv[4];
        o1.y = acc[i][5] + bv[5];
        o1.z = acc[i][6] + bv[6];
        o1.w = acc[i][7] + bv[7];
        float* cp = C + (size_t)(m0 + tm * 8 + i) * N + n0 + tn * 8;
        *(float4*)(cp)     = o0;
        *(float4*)(cp + 4) = o1;
    }
}

// ----------------------------------------------------------------------------
// Neighborhood attention. One block per (b, h, 128-query tile).
// K/V windows of the tile (<=160 keys) staged d-major in smem; 1 thread/query.
// ----------------------------------------------------------------------------
__global__ void __launch_bounds__(128) na1d_kernel(
    const float* __restrict__ qkv, float* __restrict__ outp)
{
    extern __shared__ float sh[];
    float* Ks = sh;                       // [64][PITCH]
    float* Vs = sh + 64 * PITCH;          // [64][PITCH]
    float* Sc = sh + 2 * 64 * PITCH;      // [KSZ][128]

    const int b  = blockIdx.z;
    const int h  = blockIdx.y;
    const int q0 = blockIdx.x * BQ;

    const int smin = min(max(q0 - (KSZ / 2), 0), LSEQ - KSZ);
    const int smax = min(max(q0 + BQ - 1 - (KSZ / 2), 0), LSEQ - KSZ);
    const int nk   = smax - smin + KSZ;   // <= 160

    // Stage K and V windows: Ks[d][j] = K[b, smin+j, h, d]
    const float* kb = qkv + ((size_t)(b * LSEQ + smin)) * QKVDIM + DIMSZ + h * HD;
    for (int idx = threadIdx.x; idx < nk * HD; idx += 128) {
        int j = idx >> 6;
        int d = idx & 63;
        float kv = kb[(size_t)j * QKVDIM + d];
        float vv = kb[(size_t)j * QKVDIM + DIMSZ + d];
        Ks[d * PITCH + j] = kv;
        Vs[d * PITCH + j] = vv;
    }
    __syncthreads();

    const int l   = q0 + threadIdx.x;
    const int st  = min(max(l - (KSZ / 2), 0), LSEQ - KSZ);
    const int ks0 = st - smin;

    const float* qp = qkv + ((size_t)(b * LSEQ + l)) * QKVDIM + h * HD;
    float q[HD];
#pragma unroll
    for (int d = 0; d < HD; d++) q[d] = qp[d] * 0.125f;  // SCALE = 64^-0.5

    // Scores
    float mx = -1e30f;
    for (int j = 0; j < KSZ; j++) {
        const float* kcol = Ks + ks0 + j;
        float s = 0.0f;
#pragma unroll
        for (int d = 0; d < HD; d++) s = fmaf(q[d], kcol[d * PITCH], s);
        Sc[j * 128 + threadIdx.x] = s;
        mx = fmaxf(mx, s);
    }

    // Softmax weights
    float sum = 0.0f;
    for (int j = 0; j < KSZ; j++) {
        float p = __expf(Sc[j * 128 + threadIdx.x] - mx);
        Sc[j * 128 + threadIdx.x] = p;
        sum += p;
    }
    const float inv = 1.0f / sum;

    // Weighted V accumulation
    float o[HD];
#pragma unroll
    for (int d = 0; d < HD; d++) o[d] = 0.0f;
    for (int j = 0; j < KSZ; j++) {
        float p = Sc[j * 128 + threadIdx.x];
        const float* vcol = Vs + ks0 + j;
#pragma unroll
        for (int d = 0; d < HD; d++) o[d] = fmaf(p, vcol[d * PITCH], o[d]);
    }

    float* op = outp + ((size_t)(b * LSEQ + l)) * DIMSZ + h * HD;
#pragma unroll
    for (int d = 0; d < HD; d++) op[d] = o[d] * inv;
}

// ----------------------------------------------------------------------------
// Launch
// ----------------------------------------------------------------------------
extern "C" void kernel_launch(void* const* d_in, const int* in_sizes, int n_in,
                              void* d_out, int out_size)
{
    const float* x      = (const float*)d_in[0];
    const float* w_qkv  = (const float*)d_in[1];
    const float* b_qkv  = (const float*)d_in[2];
    const float* w_proj = (const float*)d_in[3];
    const float* b_proj = (const float*)d_in[4];
    float*       out    = (float*)d_out;

    float* qkv = nullptr;
    float* att = nullptr;
    cudaGetSymbolAddress((void**)&qkv, g_qkv);
    cudaGetSymbolAddress((void**)&att, g_att);

    const int att_smem = (2 * 64 * PITCH + KSZ * 128) * sizeof(float);  // 99328 B
    cudaFuncSetAttribute(na1d_kernel,
                         cudaFuncAttributeMaxDynamicSharedMemorySize, att_smem);

    // 1) QKV projection: [8192,512] @ [1536,512]^T + b -> [8192,1536]
    dim3 g1(QKVDIM / 128, MROWS / 128);
    gemm_nt_bias<<<g1, 256>>>(x, w_qkv, b_qkv, qkv, QKVDIM, DIMSZ);

    // 2) Neighborhood attention -> [8192,512]
    dim3 g2(LSEQ / BQ, NHEADS, BATCH);
    na1d_kernel<<<g2, 128, att_smem>>>(qkv, att);

    // 3) Output projection: [8192,512] @ [512,512]^T + b -> d_out
    dim3 g3(DIMSZ / 128, MROWS / 128);
    gemm_nt_bias<<<g3, 256>>>(att, w_proj, b_proj, out, DIMSZ, DIMSZ);
}

// round 6
// speedup vs baseline: 1.6485x; 1.6485x over previous
#include <cuda_runtime.h>
#include <cuda_bf16.h>
#include <mma.h>
#include <cstdint>

using namespace nvcuda;

// Problem constants
#define BATCH   2
#define LSEQ    4096
#define DIMSZ   512
#define NHEADS  8
#define HD      64
#define KSZ     33
#define MROWS   (BATCH * LSEQ)        // 8192
#define QKVDIM  (3 * DIMSZ)           // 1536
#define KIN     512                   // inner K of both GEMMs
#define KE      (3 * KIN)             // 1536: split-bf16 expanded K
#define BQ      128
#define PITCH   161

// GEMM tiling
#define MT      128
#define NT      128
#define BKC     64                    // bf16 elems per K-chunk
#define NCHUNK  (KE / BKC)            // 24
#define SRD     72                    // smem row stride in elems (144 B, padded)
#define OP_BYTES (128 * SRD * 2)      // one operand tile: 18432 B
#define STAGE_BYTES (2 * OP_BYTES)    // A + B: 36864 B
#define SM_BIAS (2 * STAGE_BYTES)     // 73728
#define SM_TOTAL (SM_BIAS + 16 * NT * 4)  // + 8KB bias tile = 81920

// Scratch (device globals; allocation is forbidden)
__device__ float          g_qkv[(size_t)MROWS * QKVDIM];   // 50.3 MB
__device__ float          g_att[(size_t)MROWS * DIMSZ];    // 16.8 MB
__device__ __nv_bfloat16  g_a2 [(size_t)MROWS * KE];       // 25.2 MB
__device__ __nv_bfloat16  g_wq2[(size_t)QKVDIM * KE];      // 4.7 MB
__device__ __nv_bfloat16  g_wp2[(size_t)DIMSZ * KE];       // 1.6 MB

__device__ __forceinline__ uint32_t cvta_smem(const void* p) {
    uint32_t a;
    asm("{ .reg .u64 t; cvta.to.shared.u64 t, %1; cvt.u32.u64 %0, t; }"
        : "=r"(a) : "l"(p));
    return a;
}

// ---------------------------------------------------------------------------
// fp32 -> split-bf16 K-expansion.
//   mode 0 (activation side): out[row] = [hi | hi | lo]
//   mode 1 (weight side)    : out[row] = [hi | lo | hi]
// Then A2@B2^T = Ahi@Bhi + Ahi@Blo + Alo@Bhi  (drops Alo@Blo ~ 2^-16 rel)
// ---------------------------------------------------------------------------
__global__ void __launch_bounds__(256) split_bf16(
    const float* __restrict__ in, __nv_bfloat16* __restrict__ out,
    int total, int mode)
{
    int i = blockIdx.x * 256 + threadIdx.x;
    if (i >= total) return;
    int row = i >> 9;        // / 512
    int k   = i & 511;
    float x = in[i];
    __nv_bfloat16 hi = __float2bfloat16(x);
    __nv_bfloat16 lo = __float2bfloat16(x - __bfloat162float(hi));
    __nv_bfloat16* o = out + (size_t)row * KE;
    if (mode == 0) {
        o[k]            = hi;
        o[KIN + k]      = hi;
        o[2 * KIN + k]  = lo;
    } else {
        o[k]            = hi;
        o[KIN + k]      = lo;
        o[2 * KIN + k]  = hi;
    }
}

// ---------------------------------------------------------------------------
// wmma tensor-core GEMM (bf16 in, fp32 accum):
//   C[M,N] = A2[M,KE] @ B2[N,KE]^T + bias[N]
// 128x128 tile, BK=64, 2-stage cp.async pipeline, padded-stride smem,
// 8 warps (4m x 2n), warp tile 32x64 = 2x4 wmma 16x16x16 tiles.
// ---------------------------------------------------------------------------
__global__ void __launch_bounds__(256, 2) gemm_wmma(
    const __nv_bfloat16* __restrict__ A, const __nv_bfloat16* __restrict__ B,
    const float* __restrict__ bias, float* __restrict__ C, int N)
{
    extern __shared__ char sh[];
    const uint32_t sbase = cvta_smem(sh);
    float* bias_t = (float*)(sh + SM_BIAS);       // [16][NT] replicated bias

    const int tid  = threadIdx.x;
    const int wid  = tid >> 5;
    const int wm   = wid >> 1;          // 0..3  -> 32-row strip
    const int wn   = wid & 1;           // 0..1  -> 64-col strip
    const int m0 = blockIdx.y * MT;
    const int n0 = blockIdx.x * NT;

    // Replicated bias tile (16 identical rows) for accumulator init
    for (int idx = tid; idx < 16 * NT; idx += 256)
        bias_t[idx] = bias[n0 + (idx & (NT - 1))];

    const __nv_bfloat16* Ag = A + (size_t)m0 * KE;
    const __nv_bfloat16* Bg = B + (size_t)n0 * KE;

    // stage loader: per operand 128 rows x 128B (8 x 16B chunks), stride 144B
    auto load_stage = [&](int stage, int chunk) {
        const int kc = chunk * BKC;
        const uint32_t abase = sbase + stage * STAGE_BYTES;
        const uint32_t bbase = abase + OP_BYTES;
#pragma unroll
        for (int t = 0; t < 4; t++) {
            int idx = tid + t * 256;          // 0..1023
            int row = idx >> 3, c16 = idx & 7;
            uint32_t off = row * (SRD * 2) + c16 * 16;
            const void* srcA = Ag + (size_t)row * KE + kc + c16 * 8;
            asm volatile("cp.async.cg.shared.global [%0], [%1], 16;"
                         :: "r"(abase + off), "l"(srcA));
            const void* srcB = Bg + (size_t)row * KE + kc + c16 * 8;
            asm volatile("cp.async.cg.shared.global [%0], [%1], 16;"
                         :: "r"(bbase + off), "l"(srcB));
        }
    };

    // Prologue: stage 0 in flight; bias tile visible after sync
    load_stage(0, 0);
    asm volatile("cp.async.commit_group;" ::: "memory");
    __syncthreads();

    wmma::fragment<wmma::accumulator, 16, 16, 16, float> acc[2][4];
#pragma unroll
    for (int i = 0; i < 2; i++)
#pragma unroll
        for (int j = 0; j < 4; j++)
            wmma::load_matrix_sync(acc[i][j],
                                   bias_t + wn * 64 + j * 16, NT,
                                   wmma::mem_row_major);

    for (int ch = 0; ch < NCHUNK; ch++) {
        if (ch + 1 < NCHUNK) {
            load_stage((ch + 1) & 1, ch + 1);
            asm volatile("cp.async.commit_group;" ::: "memory");
            asm volatile("cp.async.wait_group 1;" ::: "memory");
        } else {
            asm volatile("cp.async.wait_group 0;" ::: "memory");
        }
        __syncthreads();

        const char* stg = sh + (ch & 1) * STAGE_BYTES;
        const __nv_bfloat16* As = (const __nv_bfloat16*)stg;
        const __nv_bfloat16* Bs = (const __nv_bfloat16*)(stg + OP_BYTES);

#pragma unroll
        for (int ks = 0; ks < 4; ks++) {
            wmma::fragment<wmma::matrix_a, 16, 16, 16, __nv_bfloat16,
                           wmma::row_major> af[2];
            wmma::fragment<wmma::matrix_b, 16, 16, 16, __nv_bfloat16,
                           wmma::col_major> bf[4];
#pragma unroll
            for (int i = 0; i < 2; i++)
                wmma::load_matrix_sync(af[i],
                    As + (size_t)(wm * 32 + i * 16) * SRD + ks * 16, SRD);
#pragma unroll
            for (int j = 0; j < 4; j++)
                wmma::load_matrix_sync(bf[j],
                    Bs + (size_t)(wn * 64 + j * 16) * SRD + ks * 16, SRD);
#pragma unroll
            for (int i = 0; i < 2; i++)
#pragma unroll
                for (int j = 0; j < 4; j++)
                    wmma::mma_sync(acc[i][j], af[i], bf[j], acc[i][j]);
        }
        __syncthreads();
    }

    // Epilogue: store fp32 (bias already folded into accumulator init)
#pragma unroll
    for (int i = 0; i < 2; i++)
#pragma unroll
        for (int j = 0; j < 4; j++)
            wmma::store_matrix_sync(
                C + (size_t)(m0 + wm * 32 + i * 16) * N + n0 + wn * 64 + j * 16,
                acc[i][j], N, wmma::mem_row_major);
}

// ---------------------------------------------------------------------------
// Neighborhood attention (unchanged from passing baseline)
// ---------------------------------------------------------------------------
__global__ void __launch_bounds__(128) na1d_kernel(
    const float* __restrict__ qkv, float* __restrict__ outp)
{
    extern __shared__ float shf[];
    float* Ks = shf;
    float* Vs = shf + 64 * PITCH;
    float* Sc = shf + 2 * 64 * PITCH;

    const int b  = blockIdx.z;
    const int h  = blockIdx.y;
    const int q0 = blockIdx.x * BQ;

    const int smin = min(max(q0 - (KSZ / 2), 0), LSEQ - KSZ);
    const int smax = min(max(q0 + BQ - 1 - (KSZ / 2), 0), LSEQ - KSZ);
    const int nk   = smax - smin + KSZ;

    const float* kb = qkv + ((size_t)(b * LSEQ + smin)) * QKVDIM + DIMSZ + h * HD;
    for (int idx = threadIdx.x; idx < nk * HD; idx += 128) {
        int j = idx >> 6;
        int d = idx & 63;
        Ks[d * PITCH + j] = kb[(size_t)j * QKVDIM + d];
        Vs[d * PITCH + j] = kb[(size_t)j * QKVDIM + DIMSZ + d];
    }
    __syncthreads();

    const int l   = q0 + threadIdx.x;
    const int st  = min(max(l - (KSZ / 2), 0), LSEQ - KSZ);
    const int ks0 = st - smin;

    const float* qp = qkv + ((size_t)(b * LSEQ + l)) * QKVDIM + h * HD;
    float q[HD];
#pragma unroll
    for (int d = 0; d < HD; d++) q[d] = qp[d] * 0.125f;

    float mx = -1e30f;
    for (int j = 0; j < KSZ; j++) {
        const float* kcol = Ks + ks0 + j;
        float s = 0.0f;
#pragma unroll
        for (int d = 0; d < HD; d++) s = fmaf(q[d], kcol[d * PITCH], s);
        Sc[j * 128 + threadIdx.x] = s;
        mx = fmaxf(mx, s);
    }

    float sum = 0.0f;
    for (int j = 0; j < KSZ; j++) {
        float p = __expf(Sc[j * 128 + threadIdx.x] - mx);
        Sc[j * 128 + threadIdx.x] = p;
        sum += p;
    }
    const float inv = 1.0f / sum;

    float o[HD];
#pragma unroll
    for (int d = 0; d < HD; d++) o[d] = 0.0f;
    for (int j = 0; j < KSZ; j++) {
        float p = Sc[j * 128 + threadIdx.x];
        const float* vcol = Vs + ks0 + j;
#pragma unroll
        for (int d = 0; d < HD; d++) o[d] = fmaf(p, vcol[d * PITCH], o[d]);
    }

    float* op = outp + ((size_t)(b * LSEQ + l)) * DIMSZ + h * HD;
#pragma unroll
    for (int d = 0; d < HD; d++) op[d] = o[d] * inv;
}

// ---------------------------------------------------------------------------
// Launch
// ---------------------------------------------------------------------------
extern "C" void kernel_launch(void* const* d_in, const int* in_sizes, int n_in,
                              void* d_out, int out_size)
{
    const float* x      = (const float*)d_in[0];
    const float* w_qkv  = (const float*)d_in[1];
    const float* b_qkv  = (const float*)d_in[2];
    const float* w_proj = (const float*)d_in[3];
    const float* b_proj = (const float*)d_in[4];
    float*       out    = (float*)d_out;

    float *qkv, *att;
    __nv_bfloat16 *a2, *wq2, *wp2;
    cudaGetSymbolAddress((void**)&qkv, g_qkv);
    cudaGetSymbolAddress((void**)&att, g_att);
    cudaGetSymbolAddress((void**)&a2,  g_a2);
    cudaGetSymbolAddress((void**)&wq2, g_wq2);
    cudaGetSymbolAddress((void**)&wp2, g_wp2);

    const int att_smem = (2 * 64 * PITCH + KSZ * 128) * sizeof(float);
    cudaFuncSetAttribute(na1d_kernel,
                         cudaFuncAttributeMaxDynamicSharedMemorySize, att_smem);
    cudaFuncSetAttribute(gemm_wmma,
                         cudaFuncAttributeMaxDynamicSharedMemorySize, SM_TOTAL);

    // Split-expand: activations [hi|hi|lo] (mode 0), weights [hi|lo|hi] (mode 1)
    split_bf16<<<(MROWS * KIN) / 256, 256>>>(x, a2, MROWS * KIN, 0);
    split_bf16<<<(QKVDIM * KIN) / 256, 256>>>(w_qkv, wq2, QKVDIM * KIN, 1);
    split_bf16<<<(DIMSZ * KIN) / 256, 256>>>(w_proj, wp2, DIMSZ * KIN, 1);

    // 1) QKV projection (tensor cores)
    dim3 g1(QKVDIM / NT, MROWS / MT);
    gemm_wmma<<<g1, 256, SM_TOTAL>>>(a2, wq2, b_qkv, qkv, QKVDIM);

    // 2) Neighborhood attention
    dim3 g2(LSEQ / BQ, NHEADS, BATCH);
    na1d_kernel<<<g2, 128, att_smem>>>(qkv, att);

    // 3) Split attention output (mode 0), then output projection
    split_bf16<<<(MROWS * KIN) / 256, 256>>>(att, a2, MROWS * KIN, 0);
    dim3 g3(DIMSZ / NT, MROWS / MT);
    gemm_wmma<<<g3, 256, SM_TOTAL>>>(a2, wp2, b_proj, out, DIMSZ);
}

// round 7
// speedup vs baseline: 1.7948x; 1.0887x over previous
#include <cuda_runtime.h>
#include <cuda_bf16.h>
#include <mma.h>
#include <cstdint>

using namespace nvcuda;

// Problem constants
#define BATCH   2
#define LSEQ    4096
#define DIMSZ   512
#define NHEADS  8
#define HD      64
#define KSZ     33
#define MROWS   (BATCH * LSEQ)        // 8192
#define QKVDIM  (3 * DIMSZ)           // 1536
#define KIN     512
#define KE      (3 * KIN)             // 1536
#define BQ      128

// GEMM tiling
#define MT      128
#define NT      128
#define BKC     64                    // bf16 elems per K-chunk
#define NCHUNK  (KE / BKC)            // 24
#define SRD     72                    // smem row stride elems (144B)
#define OP_BYTES (128 * SRD * 2)      // 18432
#define STAGE_BYTES (2 * OP_BYTES)    // 36864
#define SM_TOTAL (3 * STAGE_BYTES)    // 110592 (3 stages; bias borrows stage 2)

// Attention
#define KVP     68                    // K/V row stride in floats (272B, 16B-mult)
#define ATT_SMEM (2 * 160 * KVP * 4)  // 87040

// Scratch (device globals; allocation is forbidden)
__device__ float          g_qkv[(size_t)MROWS * QKVDIM];
__device__ float          g_att[(size_t)MROWS * DIMSZ];
__device__ __nv_bfloat16  g_a2 [(size_t)MROWS * KE];
__device__ __nv_bfloat16  g_wq2[(size_t)QKVDIM * KE];
__device__ __nv_bfloat16  g_wp2[(size_t)DIMSZ * KE];

__device__ __forceinline__ uint32_t cvta_smem(const void* p) {
    uint32_t a;
    asm("{ .reg .u64 t; cvta.to.shared.u64 t, %1; cvt.u32.u64 %0, t; }"
        : "=r"(a) : "l"(p));
    return a;
}

// ---------------------------------------------------------------------------
// fp32 -> split-bf16 K-expansion (vectorized).
//   mode 0 (activations): [hi | hi | lo]     mode 1 (weights): [hi | lo | hi]
// A2@B2^T = Ahi@Bhi + Ahi@Blo + Alo@Bhi
// ---------------------------------------------------------------------------
__global__ void __launch_bounds__(256) split_bf16(
    const float4* __restrict__ in, __nv_bfloat16* __restrict__ out,
    int total4, int mode)
{
    int i = blockIdx.x * 256 + threadIdx.x;
    if (i >= total4) return;
    int row = i >> 7;            // (i*4)/512
    int k   = (i & 127) * 4;
    float4 x = in[i];
    __nv_bfloat16 h0 = __float2bfloat16(x.x), h1 = __float2bfloat16(x.y);
    __nv_bfloat16 h2 = __float2bfloat16(x.z), h3 = __float2bfloat16(x.w);
    __nv_bfloat16 l0 = __float2bfloat16(x.x - __bfloat162float(h0));
    __nv_bfloat16 l1 = __float2bfloat16(x.y - __bfloat162float(h1));
    __nv_bfloat16 l2 = __float2bfloat16(x.z - __bfloat162float(h2));
    __nv_bfloat16 l3 = __float2bfloat16(x.w - __bfloat162float(h3));
    __nv_bfloat162 hi01 = {h0, h1}, hi23 = {h2, h3};
    __nv_bfloat162 lo01 = {l0, l1}, lo23 = {l2, l3};
    __nv_bfloat16* base = out + (size_t)row * KE;
    __nv_bfloat162* p0 = (__nv_bfloat162*)(base + k);
    __nv_bfloat162* p1 = (__nv_bfloat162*)(base + KIN + k);
    __nv_bfloat162* p2 = (__nv_bfloat162*)(base + 2 * KIN + k);
    p0[0] = hi01; p0[1] = hi23;
    if (mode == 0) {
        p1[0] = hi01; p1[1] = hi23;
        p2[0] = lo01; p2[1] = lo23;
    } else {
        p1[0] = lo01; p1[1] = lo23;
        p2[0] = hi01; p2[1] = hi23;
    }
}

// ---------------------------------------------------------------------------
// wmma tensor-core GEMM, 3-stage cp.async pipeline, ONE sync per chunk.
//   C[M,N] = A2[M,KE] @ B2[N,KE]^T + bias[N]
// ---------------------------------------------------------------------------
__global__ void __launch_bounds__(256, 2) gemm_wmma(
    const __nv_bfloat16* __restrict__ A, const __nv_bfloat16* __restrict__ B,
    const float* __restrict__ bias, float* __restrict__ C, int N)
{
    extern __shared__ char sh[];
    const uint32_t sbase = cvta_smem(sh);

    const int tid  = threadIdx.x;
    const int wid  = tid >> 5;
    const int wm   = wid >> 1;          // 0..3
    const int wn   = wid & 1;           // 0..1
    const int m0 = blockIdx.y * MT;
    const int n0 = blockIdx.x * NT;

    const __nv_bfloat16* Ag = A + (size_t)m0 * KE;
    const __nv_bfloat16* Bg = B + (size_t)n0 * KE;

    auto load_stage = [&](int stage, int chunk) {
        const int kc = chunk * BKC;
        const uint32_t abase = sbase + stage * STAGE_BYTES;
        const uint32_t bbase = abase + OP_BYTES;
#pragma unroll
        for (int t = 0; t < 4; t++) {
            int idx = tid + t * 256;
            int row = idx >> 3, c16 = idx & 7;
            uint32_t off = row * (SRD * 2) + c16 * 16;
            const void* srcA = Ag + (size_t)row * KE + kc + c16 * 8;
            asm volatile("cp.async.cg.shared.global [%0], [%1], 16;"
                         :: "r"(abase + off), "l"(srcA));
            const void* srcB = Bg + (size_t)row * KE + kc + c16 * 8;
            asm volatile("cp.async.cg.shared.global [%0], [%1], 16;"
                         :: "r"(bbase + off), "l"(srcB));
        }
    };

    // Prologue: stages 0,1 in flight; bias tile staged in stage-2 region
    load_stage(0, 0);
    asm volatile("cp.async.commit_group;" ::: "memory");
    load_stage(1, 1);
    asm volatile("cp.async.commit_group;" ::: "memory");

    float* bias_t = (float*)(sh + 2 * STAGE_BYTES);   // [16][NT] replicated
    for (int idx = tid; idx < 16 * NT; idx += 256)
        bias_t[idx] = bias[n0 + (idx & (NT - 1))];
    __syncthreads();

    wmma::fragment<wmma::accumulator, 16, 16, 16, float> acc[2][4];
#pragma unroll
    for (int i = 0; i < 2; i++)
#pragma unroll
        for (int j = 0; j < 4; j++)
            wmma::load_matrix_sync(acc[i][j],
                                   bias_t + wn * 64 + j * 16, NT,
                                   wmma::mem_row_major);

    for (int ch = 0; ch < NCHUNK; ch++) {
        asm volatile("cp.async.wait_group 1;" ::: "memory");
        __syncthreads();   // stage ch resident; all warps done with stage ch-1

        const char* stg = sh + (ch % 3) * STAGE_BYTES;
        const __nv_bfloat16* As = (const __nv_bfloat16*)stg;
        const __nv_bfloat16* Bs = (const __nv_bfloat16*)(stg + OP_BYTES);

#pragma unroll
        for (int ks = 0; ks < 4; ks++) {
            wmma::fragment<wmma::matrix_a, 16, 16, 16, __nv_bfloat16,
                           wmma::row_major> af[2];
            wmma::fragment<wmma::matrix_b, 16, 16, 16, __nv_bfloat16,
                           wmma::col_major> bf[4];
#pragma unroll
            for (int i = 0; i < 2; i++)
                wmma::load_matrix_sync(af[i],
                    As + (size_t)(wm * 32 + i * 16) * SRD + ks * 16, SRD);
#pragma unroll
            for (int j = 0; j < 4; j++)
                wmma::load_matrix_sync(bf[j],
                    Bs + (size_t)(wn * 64 + j * 16) * SRD + ks * 16, SRD);
#pragma unroll
            for (int i = 0; i < 2; i++)
#pragma unroll
                for (int j = 0; j < 4; j++)
                    wmma::mma_sync(acc[i][j], af[i], bf[j], acc[i][j]);
        }

        // Issue next load into stage (ch+2)%3 — that buffer held chunk ch-1,
        // which every warp finished before this iteration's __syncthreads.
        const int nc = ch + 2;
        if (nc < NCHUNK) load_stage(nc % 3, nc);
        asm volatile("cp.async.commit_group;" ::: "memory");
    }

    // Epilogue (bias folded into accumulator init)
#pragma unroll
    for (int i = 0; i < 2; i++)
#pragma unroll
        for (int j = 0; j < 4; j++)
            wmma::store_matrix_sync(
                C + (size_t)(m0 + wm * 32 + i * 16) * N + n0 + wn * 64 + j * 16,
                acc[i][j], N, wmma::mem_row_major);
}

// ---------------------------------------------------------------------------
// Neighborhood attention: 4 threads per query (512 threads, 128 queries/blk).
// K/V row-major [j][d] (stride 68 floats), float4 LDS, scores in registers,
// d-partition combine via shfl butterfly.
// ---------------------------------------------------------------------------
__global__ void __launch_bounds__(512) na1d_kernel(
    const float* __restrict__ qkv, float* __restrict__ outp)
{
    extern __shared__ float shf[];
    float* Ks = shf;                  // [160][KVP]
    float* Vs = shf + 160 * KVP;      // [160][KVP]

    const int tid = threadIdx.x;
    const int b  = blockIdx.z;
    const int h  = blockIdx.y;
    const int q0 = blockIdx.x * BQ;

    const int smin = min(max(q0 - (KSZ / 2), 0), LSEQ - KSZ);
    const int smax = min(max(q0 + BQ - 1 - (KSZ / 2), 0), LSEQ - KSZ);
    const int nk   = smax - smin + KSZ;   // <= 160

    // Stage K/V rows (float4, coalesced)
    const float* kb = qkv + ((size_t)(b * LSEQ + smin)) * QKVDIM + DIMSZ + h * HD;
    for (int idx = tid; idx < nk * 16; idx += 512) {
        int j = idx >> 4;
        int s = (idx & 15) * 4;
        *(float4*)(Ks + j * KVP + s) = *(const float4*)(kb + (size_t)j * QKVDIM + s);
        *(float4*)(Vs + j * KVP + s) = *(const float4*)(kb + (size_t)j * QKVDIM + DIMSZ + s);
    }
    __syncthreads();

    const int l  = q0 + (tid >> 2);         // query index
    const int dp = (tid & 3) * 16;          // this thread's 16-dim slice
    const int st  = min(max(l - (KSZ / 2), 0), LSEQ - KSZ);
    const int ks0 = st - smin;

    const float* qp = qkv + ((size_t)(b * LSEQ + l)) * QKVDIM + h * HD + dp;
    float qv[16];
#pragma unroll
    for (int s = 0; s < 16; s += 4) {
        float4 v = *(const float4*)(qp + s);
        qv[s] = v.x * 0.125f; qv[s+1] = v.y * 0.125f;
        qv[s+2] = v.z * 0.125f; qv[s+3] = v.w * 0.125f;
    }

    float sc[KSZ];
    float mx = -1e30f;
#pragma unroll
    for (int j = 0; j < KSZ; j++) {
        const float* kr = Ks + (ks0 + j) * KVP + dp;
        float p = 0.0f;
#pragma unroll
        for (int s = 0; s < 16; s += 4) {
            float4 v = *(const float4*)(kr + s);
            p = fmaf(qv[s], v.x, p);   p = fmaf(qv[s+1], v.y, p);
            p = fmaf(qv[s+2], v.z, p); p = fmaf(qv[s+3], v.w, p);
        }
        p += __shfl_xor_sync(0xFFFFFFFF, p, 1);
        p += __shfl_xor_sync(0xFFFFFFFF, p, 2);
        sc[j] = p;
        mx = fmaxf(mx, p);
    }

    float sum = 0.0f;
#pragma unroll
    for (int j = 0; j < KSZ; j++) {
        float p = __expf(sc[j] - mx);
        sc[j] = p;
        sum += p;
    }
    const float inv = 1.0f / sum;

    float o[16];
#pragma unroll
    for (int s = 0; s < 16; s++) o[s] = 0.0f;
#pragma unroll
    for (int j = 0; j < KSZ; j++) {
        const float p = sc[j];
        const float* vr = Vs + (ks0 + j) * KVP + dp;
#pragma unroll
        for (int s = 0; s < 16; s += 4) {
            float4 v = *(const float4*)(vr + s);
            o[s]   = fmaf(p, v.x, o[s]);   o[s+1] = fmaf(p, v.y, o[s+1]);
            o[s+2] = fmaf(p, v.z, o[s+2]); o[s+3] = fmaf(p, v.w, o[s+3]);
        }
    }

    float* op = outp + ((size_t)(b * LSEQ + l)) * DIMSZ + h * HD + dp;
#pragma unroll
    for (int s = 0; s < 16; s += 4) {
        float4 v;
        v.x = o[s] * inv; v.y = o[s+1] * inv;
        v.z = o[s+2] * inv; v.w = o[s+3] * inv;
        *(float4*)(op + s) = v;
    }
}

// ---------------------------------------------------------------------------
// Launch
// ---------------------------------------------------------------------------
extern "C" void kernel_launch(void* const* d_in, const int* in_sizes, int n_in,
                              void* d_out, int out_size)
{
    const float* x      = (const float*)d_in[0];
    const float* w_qkv  = (const float*)d_in[1];
    const float* b_qkv  = (const float*)d_in[2];
    const float* w_proj = (const float*)d_in[3];
    const float* b_proj = (const float*)d_in[4];
    float*       out    = (float*)d_out;

    float *qkv, *att;
    __nv_bfloat16 *a2, *wq2, *wp2;
    cudaGetSymbolAddress((void**)&qkv, g_qkv);
    cudaGetSymbolAddress((void**)&att, g_att);
    cudaGetSymbolAddress((void**)&a2,  g_a2);
    cudaGetSymbolAddress((void**)&wq2, g_wq2);
    cudaGetSymbolAddress((void**)&wp2, g_wp2);

    cudaFuncSetAttribute(na1d_kernel,
                         cudaFuncAttributeMaxDynamicSharedMemorySize, ATT_SMEM);
    cudaFuncSetAttribute(gemm_wmma,
                         cudaFuncAttributeMaxDynamicSharedMemorySize, SM_TOTAL);

    // Split-expand: activations mode 0, weights mode 1
    split_bf16<<<(MROWS * KIN / 4) / 256, 256>>>((const float4*)x, a2,
                                                 MROWS * KIN / 4, 0);
    split_bf16<<<(QKVDIM * KIN / 4) / 256, 256>>>((const float4*)w_qkv, wq2,
                                                  QKVDIM * KIN / 4, 1);
    split_bf16<<<(DIMSZ * KIN / 4) / 256, 256>>>((const float4*)w_proj, wp2,
                                                 DIMSZ * KIN / 4, 1);

    // 1) QKV projection
    dim3 g1(QKVDIM / NT, MROWS / MT);
    gemm_wmma<<<g1, 256, SM_TOTAL>>>(a2, wq2, b_qkv, qkv, QKVDIM);

    // 2) Neighborhood attention
    dim3 g2(LSEQ / BQ, NHEADS, BATCH);
    na1d_kernel<<<g2, 512, ATT_SMEM>>>(qkv, att);

    // 3) Split attention output, then output projection
    split_bf16<<<(MROWS * KIN / 4) / 256, 256>>>((const float4*)att, a2,
                                                 MROWS * KIN / 4, 0);
    dim3 g3(DIMSZ / NT, MROWS / MT);
    gemm_wmma<<<g3, 256, SM_TOTAL>>>(a2, wp2, b_proj, out, DIMSZ);
}

// round 8
// speedup vs baseline: 1.8697x; 1.0418x over previous
#include <cuda_runtime.h>
#include <cuda_bf16.h>
#include <mma.h>
#include <cstdint>

using namespace nvcuda;

// Problem constants
#define BATCH   2
#define LSEQ    4096
#define DIMSZ   512
#define NHEADS  8
#define HD      64
#define KSZ     33
#define MROWS   (BATCH * LSEQ)        // 8192
#define QKVDIM  (3 * DIMSZ)           // 1536
#define KIN     512
#define KE      (3 * KIN)             // 1536
#define BQ      128

// GEMM tiling: CTA 128x256, 8 warps (2x4), warp tile 64x64
#define MT      128
#define NT      256
#define BKC     64                    // bf16 elems per K-chunk
#define NCHUNK  (KE / BKC)            // 24
#define SRD     72                    // smem row stride elems (144B)
#define A_BYTES (128 * SRD * 2)       // 18432
#define B_BYTES (256 * SRD * 2)       // 36864
#define STAGE_BYTES (A_BYTES + B_BYTES)   // 55296
#define SM_TOTAL (3 * STAGE_BYTES)        // 165888 (bias borrows stage 2)

// Attention
#define KVP     68                    // K/V row stride floats (272B)
#define ATT_SMEM (2 * 160 * KVP * 4)  // 87040

// Scratch (device globals; allocation is forbidden)
__device__ float          g_qkv[(size_t)MROWS * QKVDIM];
__device__ float          g_att[(size_t)MROWS * DIMSZ];
__device__ __nv_bfloat16  g_a2 [(size_t)MROWS * KE];
__device__ __nv_bfloat16  g_wq2[(size_t)QKVDIM * KE];
__device__ __nv_bfloat16  g_wp2[(size_t)DIMSZ * KE];

__device__ __forceinline__ uint32_t cvta_smem(const void* p) {
    uint32_t a;
    asm("{ .reg .u64 t; cvta.to.shared.u64 t, %1; cvt.u32.u64 %0, t; }"
        : "=r"(a) : "l"(p));
    return a;
}

// ---------------------------------------------------------------------------
// fp32 -> split-bf16 K-expansion (vectorized).
//   mode 0 (activations): [hi | hi | lo]     mode 1 (weights): [hi | lo | hi]
// A2@B2^T = Ahi@Bhi + Ahi@Blo + Alo@Bhi
// ---------------------------------------------------------------------------
__global__ void __launch_bounds__(256) split_bf16(
    const float4* __restrict__ in, __nv_bfloat16* __restrict__ out,
    int total4, int mode)
{
    int i = blockIdx.x * 256 + threadIdx.x;
    if (i >= total4) return;
    int row = i >> 7;
    int k   = (i & 127) * 4;
    float4 x = in[i];
    __nv_bfloat16 h0 = __float2bfloat16(x.x), h1 = __float2bfloat16(x.y);
    __nv_bfloat16 h2 = __float2bfloat16(x.z), h3 = __float2bfloat16(x.w);
    __nv_bfloat16 l0 = __float2bfloat16(x.x - __bfloat162float(h0));
    __nv_bfloat16 l1 = __float2bfloat16(x.y - __bfloat162float(h1));
    __nv_bfloat16 l2 = __float2bfloat16(x.z - __bfloat162float(h2));
    __nv_bfloat16 l3 = __float2bfloat16(x.w - __bfloat162float(h3));
    __nv_bfloat162 hi01 = {h0, h1}, hi23 = {h2, h3};
    __nv_bfloat162 lo01 = {l0, l1}, lo23 = {l2, l3};
    __nv_bfloat16* base = out + (size_t)row * KE;
    __nv_bfloat162* p0 = (__nv_bfloat162*)(base + k);
    __nv_bfloat162* p1 = (__nv_bfloat162*)(base + KIN + k);
    __nv_bfloat162* p2 = (__nv_bfloat162*)(base + 2 * KIN + k);
    p0[0] = hi01; p0[1] = hi23;
    if (mode == 0) {
        p1[0] = hi01; p1[1] = hi23;
        p2[0] = lo01; p2[1] = lo23;
    } else {
        p1[0] = lo01; p1[1] = lo23;
        p2[0] = hi01; p2[1] = hi23;
    }
}

// ---------------------------------------------------------------------------
// wmma tensor-core GEMM: C[M,N] = A2[M,KE] @ B2[N,KE]^T + bias[N]
// CTA tile 128x256, warp tile 64x64, 3-stage cp.async, one sync per chunk.
// ---------------------------------------------------------------------------
__global__ void __launch_bounds__(256, 1) gemm_wmma(
    const __nv_bfloat16* __restrict__ A, const __nv_bfloat16* __restrict__ B,
    const float* __restrict__ bias, float* __restrict__ C, int N)
{
    extern __shared__ char sh[];
    const uint32_t sbase = cvta_smem(sh);

    const int tid  = threadIdx.x;
    const int wid  = tid >> 5;
    const int wm   = wid >> 2;          // 0..1  -> 64-row strip
    const int wn   = wid & 3;           // 0..3  -> 64-col strip
    const int m0 = blockIdx.y * MT;
    const int n0 = blockIdx.x * NT;

    const __nv_bfloat16* Ag = A + (size_t)m0 * KE;
    const __nv_bfloat16* Bg = B + (size_t)n0 * KE;

    // stage loader: A 128 rows + B 256 rows, 8 x 16B chunks per row
    auto load_stage = [&](int stage, int chunk) {
        const int kc = chunk * BKC;
        const uint32_t abase = sbase + stage * STAGE_BYTES;
        const uint32_t bbase = abase + A_BYTES;
#pragma unroll
        for (int t = 0; t < 4; t++) {                 // A: 1024 ops
            int idx = tid + t * 256;
            int row = idx >> 3, c16 = idx & 7;
            uint32_t off = row * (SRD * 2) + c16 * 16;
            const void* src = Ag + (size_t)row * KE + kc + c16 * 8;
            asm volatile("cp.async.cg.shared.global [%0], [%1], 16;"
                         :: "r"(abase + off), "l"(src));
        }
#pragma unroll
        for (int t = 0; t < 8; t++) {                 // B: 2048 ops
            int idx = tid + t * 256;
            int row = idx >> 3, c16 = idx & 7;
            uint32_t off = row * (SRD * 2) + c16 * 16;
            const void* src = Bg + (size_t)row * KE + kc + c16 * 8;
            asm volatile("cp.async.cg.shared.global [%0], [%1], 16;"
                         :: "r"(bbase + off), "l"(src));
        }
    };

    // Prologue: stages 0,1 in flight; bias tile staged in stage-2 region
    load_stage(0, 0);
    asm volatile("cp.async.commit_group;" ::: "memory");
    load_stage(1, 1);
    asm volatile("cp.async.commit_group;" ::: "memory");

    float* bias_t = (float*)(sh + 2 * STAGE_BYTES);   // [16][NT] replicated
    for (int idx = tid; idx < 16 * NT; idx += 256)
        bias_t[idx] = bias[n0 + (idx & (NT - 1))];
    __syncthreads();

    wmma::fragment<wmma::accumulator, 16, 16, 16, float> acc[4][4];
#pragma unroll
    for (int i = 0; i < 4; i++)
#pragma unroll
        for (int j = 0; j < 4; j++)
            wmma::load_matrix_sync(acc[i][j],
                                   bias_t + wn * 64 + j * 16, NT,
                                   wmma::mem_row_major);

    for (int ch = 0; ch < NCHUNK; ch++) {
        asm volatile("cp.async.wait_group 1;" ::: "memory");
        __syncthreads();   // stage ch resident; all warps done with ch-1

        const char* stg = sh + (ch % 3) * STAGE_BYTES;
        const __nv_bfloat16* As = (const __nv_bfloat16*)stg;
        const __nv_bfloat16* Bs = (const __nv_bfloat16*)(stg + A_BYTES);

#pragma unroll
        for (int ks = 0; ks < 4; ks++) {
            wmma::fragment<wmma::matrix_a, 16, 16, 16, __nv_bfloat16,
                           wmma::row_major> af[4];
            wmma::fragment<wmma::matrix_b, 16, 16, 16, __nv_bfloat16,
                           wmma::col_major> bf[4];
#pragma unroll
            for (int i = 0; i < 4; i++)
                wmma::load_matrix_sync(af[i],
                    As + (size_t)(wm * 64 + i * 16) * SRD + ks * 16, SRD);
#pragma unroll
            for (int j = 0; j < 4; j++)
                wmma::load_matrix_sync(bf[j],
                    Bs + (size_t)(wn * 64 + j * 16) * SRD + ks * 16, SRD);
#pragma unroll
            for (int i = 0; i < 4; i++)
#pragma unroll
                for (int j = 0; j < 4; j++)
                    wmma::mma_sync(acc[i][j], af[i], bf[j], acc[i][j]);
        }

        const int nc = ch + 2;
        if (nc < NCHUNK) load_stage(nc % 3, nc);
        asm volatile("cp.async.commit_group;" ::: "memory");
    }

    // Epilogue (bias folded into accumulator init)
#pragma unroll
    for (int i = 0; i < 4; i++)
#pragma unroll
        for (int j = 0; j < 4; j++)
            wmma::store_matrix_sync(
                C + (size_t)(m0 + wm * 64 + i * 16) * N + n0 + wn * 64 + j * 16,
                acc[i][j], N, wmma::mem_row_major);
}

// ---------------------------------------------------------------------------
// Neighborhood attention: 4 threads per query (512 threads, 128 queries/blk).
// ---------------------------------------------------------------------------
__global__ void __launch_bounds__(512) na1d_kernel(
    const float* __restrict__ qkv, float* __restrict__ outp)
{
    extern __shared__ float shf[];
    float* Ks = shf;                  // [160][KVP]
    float* Vs = shf + 160 * KVP;

    const int tid = threadIdx.x;
    const int b  = blockIdx.z;
    const int h  = blockIdx.y;
    const int q0 = blockIdx.x * BQ;

    const int smin = min(max(q0 - (KSZ / 2), 0), LSEQ - KSZ);
    const int smax = min(max(q0 + BQ - 1 - (KSZ / 2), 0), LSEQ - KSZ);
    const int nk   = smax - smin + KSZ;   // <= 160

    const float* kb = qkv + ((size_t)(b * LSEQ + smin)) * QKVDIM + DIMSZ + h * HD;
    for (int idx = tid; idx < nk * 16; idx += 512) {
        int j = idx >> 4;
        int s = (idx & 15) * 4;
        *(float4*)(Ks + j * KVP + s) = *(const float4*)(kb + (size_t)j * QKVDIM + s);
        *(float4*)(Vs + j * KVP + s) = *(const float4*)(kb + (size_t)j * QKVDIM + DIMSZ + s);
    }
    __syncthreads();

    const int l  = q0 + (tid >> 2);
    const int dp = (tid & 3) * 16;
    const int st  = min(max(l - (KSZ / 2), 0), LSEQ - KSZ);
    const int ks0 = st - smin;

    const float* qp = qkv + ((size_t)(b * LSEQ + l)) * QKVDIM + h * HD + dp;
    float qv[16];
#pragma unroll
    for (int s = 0; s < 16; s += 4) {
        float4 v = *(const float4*)(qp + s);
        qv[s] = v.x * 0.125f; qv[s+1] = v.y * 0.125f;
        qv[s+2] = v.z * 0.125f; qv[s+3] = v.w * 0.125f;
    }

    float sc[KSZ];
    float mx = -1e30f;
#pragma unroll
    for (int j = 0; j < KSZ; j++) {
        const float* kr = Ks + (ks0 + j) * KVP + dp;
        float p = 0.0f;
#pragma unroll
        for (int s = 0; s < 16; s += 4) {
            float4 v = *(const float4*)(kr + s);
            p = fmaf(qv[s], v.x, p);   p = fmaf(qv[s+1], v.y, p);
            p = fmaf(qv[s+2], v.z, p); p = fmaf(qv[s+3], v.w, p);
        }
        p += __shfl_xor_sync(0xFFFFFFFF, p, 1);
        p += __shfl_xor_sync(0xFFFFFFFF, p, 2);
        sc[j] = p;
        mx = fmaxf(mx, p);
    }

    float sum = 0.0f;
#pragma unroll
    for (int j = 0; j < KSZ; j++) {
        float p = __expf(sc[j] - mx);
        sc[j] = p;
        sum += p;
    }
    const float inv = 1.0f / sum;

    float o[16];
#pragma unroll
    for (int s = 0; s < 16; s++) o[s] = 0.0f;
#pragma unroll
    for (int j = 0; j < KSZ; j++) {
        const float p = sc[j];
        const float* vr = Vs + (ks0 + j) * KVP + dp;
#pragma unroll
        for (int s = 0; s < 16; s += 4) {
            float4 v = *(const float4*)(vr + s);
            o[s]   = fmaf(p, v.x, o[s]);   o[s+1] = fmaf(p, v.y, o[s+1]);
            o[s+2] = fmaf(p, v.z, o[s+2]); o[s+3] = fmaf(p, v.w, o[s+3]);
        }
    }

    float* op = outp + ((size_t)(b * LSEQ + l)) * DIMSZ + h * HD + dp;
#pragma unroll
    for (int s = 0; s < 16; s += 4) {
        float4 v;
        v.x = o[s] * inv; v.y = o[s+1] * inv;
        v.z = o[s+2] * inv; v.w = o[s+3] * inv;
        *(float4*)(op + s) = v;
    }
}

// ---------------------------------------------------------------------------
// Launch
// ---------------------------------------------------------------------------
extern "C" void kernel_launch(void* const* d_in, const int* in_sizes, int n_in,
                              void* d_out, int out_size)
{
    const float* x      = (const float*)d_in[0];
    const float* w_qkv  = (const float*)d_in[1];
    const float* b_qkv  = (const float*)d_in[2];
    const float* w_proj = (const float*)d_in[3];
    const float* b_proj = (const float*)d_in[4];
    float*       out    = (float*)d_out;

    float *qkv, *att;
    __nv_bfloat16 *a2, *wq2, *wp2;
    cudaGetSymbolAddress((void**)&qkv, g_qkv);
    cudaGetSymbolAddress((void**)&att, g_att);
    cudaGetSymbolAddress((void**)&a2,  g_a2);
    cudaGetSymbolAddress((void**)&wq2, g_wq2);
    cudaGetSymbolAddress((void**)&wp2, g_wp2);

    cudaFuncSetAttribute(na1d_kernel,
                         cudaFuncAttributeMaxDynamicSharedMemorySize, ATT_SMEM);
    cudaFuncSetAttribute(gemm_wmma,
                         cudaFuncAttributeMaxDynamicSharedMemorySize, SM_TOTAL);

    // Split-expand: activations mode 0, weights mode 1
    split_bf16<<<(MROWS * KIN / 4) / 256, 256>>>((const float4*)x, a2,
                                                 MROWS * KIN / 4, 0);
    split_bf16<<<(QKVDIM * KIN / 4) / 256, 256>>>((const float4*)w_qkv, wq2,
                                                  QKVDIM * KIN / 4, 1);
    split_bf16<<<(DIMSZ * KIN / 4) / 256, 256>>>((const float4*)w_proj, wp2,
                                                 DIMSZ * KIN / 4, 1);

    // 1) QKV projection
    dim3 g1(QKVDIM / NT, MROWS / MT);
    gemm_wmma<<<g1, 256, SM_TOTAL>>>(a2, wq2, b_qkv, qkv, QKVDIM);

    // 2) Neighborhood attention
    dim3 g2(LSEQ / BQ, NHEADS, BATCH);
    na1d_kernel<<<g2, 512, ATT_SMEM>>>(qkv, att);

    // 3) Split attention output, then output projection
    split_bf16<<<(MROWS * KIN / 4) / 256, 256>>>((const float4*)att, a2,
                                                 MROWS * KIN / 4, 0);
    dim3 g3(DIMSZ / NT, MROWS / MT);
    gemm_wmma<<<g3, 256, SM_TOTAL>>>(a2, wp2, b_proj, out, DIMSZ);
}

// round 9
// speedup vs baseline: 1.9429x; 1.0391x over previous
#include <cuda_runtime.h>
#include <cuda_bf16.h>
#include <mma.h>
#include <cstdint>

using namespace nvcuda;

// Problem constants
#define BATCH   2
#define LSEQ    4096
#define DIMSZ   512
#define NHEADS  8
#define HD      64
#define KSZ     33
#define MROWS   (BATCH * LSEQ)        // 8192
#define QKVDIM  (3 * DIMSZ)           // 1536
#define KIN     512
#define K2      1024                  // [hi|lo] compact layout
#define BQ      128

// GEMM tiling: CTA 128x256, 16 warps (4x4), warp tile 32x64
#define MT      128
#define NT      256
#define KC      64                    // bf16 elems per K-step
#define NIT     (KIN / KC)            // 8 iterations
#define SRD     72                    // smem row stride elems (144B)
#define AT_B    (128 * SRD * 2)       // one A tile: 18432
#define BT_B    (256 * SRD * 2)       // one B tile: 36864
#define STAGE_BYTES (2 * AT_B + 2 * BT_B)   // Ahi+Alo+Bhi+Blo = 110592
#define SM_TOTAL (2 * STAGE_BYTES)          // 221184 (fits 227KB)

// Attention
#define KVP     68
#define ATT_SMEM (2 * 160 * KVP * 4)  // 87040

// Scratch (device globals; allocation is forbidden)
__device__ float          g_qkv[(size_t)MROWS * QKVDIM];
__device__ float          g_att[(size_t)MROWS * DIMSZ];
__device__ __nv_bfloat16  g_a2 [(size_t)MROWS * K2];     // [hi|lo]
__device__ __nv_bfloat16  g_wq2[(size_t)QKVDIM * K2];
__device__ __nv_bfloat16  g_wp2[(size_t)DIMSZ * K2];

__device__ __forceinline__ uint32_t cvta_smem(const void* p) {
    uint32_t a;
    asm("{ .reg .u64 t; cvta.to.shared.u64 t, %1; cvt.u32.u64 %0, t; }"
        : "=r"(a) : "l"(p));
    return a;
}

// ---------------------------------------------------------------------------
// fp32 -> compact split-bf16: out[row, 0:512] = hi, out[row, 512:1024] = lo
// ---------------------------------------------------------------------------
__global__ void __launch_bounds__(256) split_bf16(
    const float4* __restrict__ in, __nv_bfloat16* __restrict__ out, int total4)
{
    int i = blockIdx.x * 256 + threadIdx.x;
    if (i >= total4) return;
    int row = i >> 7;
    int k   = (i & 127) * 4;
    float4 x = in[i];
    __nv_bfloat16 h0 = __float2bfloat16(x.x), h1 = __float2bfloat16(x.y);
    __nv_bfloat16 h2 = __float2bfloat16(x.z), h3 = __float2bfloat16(x.w);
    __nv_bfloat16 l0 = __float2bfloat16(x.x - __bfloat162float(h0));
    __nv_bfloat16 l1 = __float2bfloat16(x.y - __bfloat162float(h1));
    __nv_bfloat16 l2 = __float2bfloat16(x.z - __bfloat162float(h2));
    __nv_bfloat16 l3 = __float2bfloat16(x.w - __bfloat162float(h3));
    __nv_bfloat16* base = out + (size_t)row * K2;
    __nv_bfloat162* ph = (__nv_bfloat162*)(base + k);
    __nv_bfloat162* pl = (__nv_bfloat162*)(base + KIN + k);
    ph[0] = {h0, h1}; ph[1] = {h2, h3};
    pl[0] = {l0, l1}; pl[1] = {l2, l3};
}

// ---------------------------------------------------------------------------
// wmma GEMM with 3-term split accumulation:
//   C = Ahi@Bhi^T + Ahi@Blo^T + Alo@Bhi^T + bias
// Per iteration: load 4 unique tiles (Ahi,Alo,Bhi,Blo), double-buffered.
// 512 threads = 16 warps (4x4), warp tile 32x64.
// ---------------------------------------------------------------------------
__global__ void __launch_bounds__(512, 1) gemm_wmma(
    const __nv_bfloat16* __restrict__ A, const __nv_bfloat16* __restrict__ B,
    const float* __restrict__ bias, float* __restrict__ C, int N)
{
    extern __shared__ char sh[];
    const uint32_t sbase = cvta_smem(sh);

    const int tid  = threadIdx.x;
    const int wid  = tid >> 5;
    const int wm   = wid >> 2;          // 0..3 -> 32-row strip
    const int wn   = wid & 3;           // 0..3 -> 64-col strip
    const int m0 = blockIdx.y * MT;
    const int n0 = blockIdx.x * NT;

    const __nv_bfloat16* Ag = A + (size_t)m0 * K2;
    const __nv_bfloat16* Bg = B + (size_t)n0 * K2;

    // Stage bias tile (16 replicated rows) in stage-0 region, init accumulators
    float* bias_t = (float*)sh;
    for (int idx = tid; idx < 16 * NT; idx += 512)
        bias_t[idx] = bias[n0 + (idx & (NT - 1))];
    __syncthreads();

    wmma::fragment<wmma::accumulator, 16, 16, 16, float> acc[2][4];
#pragma unroll
    for (int i = 0; i < 2; i++)
#pragma unroll
        for (int j = 0; j < 4; j++)
            wmma::load_matrix_sync(acc[i][j],
                                   bias_t + wn * 64 + j * 16, NT,
                                   wmma::mem_row_major);
    __syncthreads();   // bias region about to be overwritten by stage 0

    // stage loader: 4 tiles. A: 2048 16B chunks (hi+lo), B: 4096.
    auto load_stage = [&](int stage, int it) {
        const int kc = it * KC;
        const uint32_t s0 = sbase + stage * STAGE_BYTES;
#pragma unroll
        for (int t = 0; t < 4; t++) {                 // A hi+lo
            int idx = tid + t * 512;                  // 0..2047
            int half = idx >> 10;                     // 0=hi, 1=lo
            int row  = (idx >> 3) & 127;
            int c16  = idx & 7;
            uint32_t dst = s0 + half * AT_B + row * (SRD * 2) + c16 * 16;
            const void* src = Ag + (size_t)row * K2 + half * KIN + kc + c16 * 8;
            asm volatile("cp.async.cg.shared.global [%0], [%1], 16;"
                         :: "r"(dst), "l"(src));
        }
#pragma unroll
        for (int t = 0; t < 8; t++) {                 // B hi+lo
            int idx = tid + t * 512;                  // 0..4095
            int half = idx >> 11;
            int row  = (idx >> 3) & 255;
            int c16  = idx & 7;
            uint32_t dst = s0 + 2 * AT_B + half * BT_B + row * (SRD * 2) + c16 * 16;
            const void* src = Bg + (size_t)row * K2 + half * KIN + kc + c16 * 8;
            asm volatile("cp.async.cg.shared.global [%0], [%1], 16;"
                         :: "r"(dst), "l"(src));
        }
    };

    load_stage(0, 0);
    asm volatile("cp.async.commit_group;" ::: "memory");
    if (NIT > 1) {
        load_stage(1, 1);
        asm volatile("cp.async.commit_group;" ::: "memory");
    }

    for (int it = 0; it < NIT; it++) {
        if (it + 1 < NIT)
            asm volatile("cp.async.wait_group 1;" ::: "memory");
        else
            asm volatile("cp.async.wait_group 0;" ::: "memory");
        __syncthreads();

        const char* stg = sh + (it & 1) * STAGE_BYTES;
        const __nv_bfloat16* Ahi = (const __nv_bfloat16*)stg;
        const __nv_bfloat16* Alo = (const __nv_bfloat16*)(stg + AT_B);
        const __nv_bfloat16* Bhi = (const __nv_bfloat16*)(stg + 2 * AT_B);
        const __nv_bfloat16* Blo = (const __nv_bfloat16*)(stg + 2 * AT_B + BT_B);

#pragma unroll
        for (int ks = 0; ks < 4; ks++) {
            wmma::fragment<wmma::matrix_a, 16, 16, 16, __nv_bfloat16,
                           wmma::row_major> af[2];
            wmma::fragment<wmma::matrix_b, 16, 16, 16, __nv_bfloat16,
                           wmma::col_major> bfh[4], bfl[4];
            // Ahi fragments
#pragma unroll
            for (int i = 0; i < 2; i++)
                wmma::load_matrix_sync(af[i],
                    Ahi + (size_t)(wm * 32 + i * 16) * SRD + ks * 16, SRD);
            // Bhi fragments; term 1: Ahi@Bhi
#pragma unroll
            for (int j = 0; j < 4; j++)
                wmma::load_matrix_sync(bfh[j],
                    Bhi + (size_t)(wn * 64 + j * 16) * SRD + ks * 16, SRD);
#pragma unroll
            for (int i = 0; i < 2; i++)
#pragma unroll
                for (int j = 0; j < 4; j++)
                    wmma::mma_sync(acc[i][j], af[i], bfh[j], acc[i][j]);
            // Blo fragments; term 2: Ahi@Blo
#pragma unroll
            for (int j = 0; j < 4; j++)
                wmma::load_matrix_sync(bfl[j],
                    Blo + (size_t)(wn * 64 + j * 16) * SRD + ks * 16, SRD);
#pragma unroll
            for (int i = 0; i < 2; i++)
#pragma unroll
                for (int j = 0; j < 4; j++)
                    wmma::mma_sync(acc[i][j], af[i], bfl[j], acc[i][j]);
            // Alo fragments (reuse af); term 3: Alo@Bhi
#pragma unroll
            for (int i = 0; i < 2; i++)
                wmma::load_matrix_sync(af[i],
                    Alo + (size_t)(wm * 32 + i * 16) * SRD + ks * 16, SRD);
#pragma unroll
            for (int i = 0; i < 2; i++)
#pragma unroll
                for (int j = 0; j < 4; j++)
                    wmma::mma_sync(acc[i][j], af[i], bfh[j], acc[i][j]);
        }
        __syncthreads();   // all warps done with this buffer

        const int nx = it + 2;
        if (nx < NIT) {
            load_stage(nx & 1, nx);
            asm volatile("cp.async.commit_group;" ::: "memory");
        }
    }

    // Epilogue (bias already in accumulators)
#pragma unroll
    for (int i = 0; i < 2; i++)
#pragma unroll
        for (int j = 0; j < 4; j++)
            wmma::store_matrix_sync(
                C + (size_t)(m0 + wm * 32 + i * 16) * N + n0 + wn * 64 + j * 16,
                acc[i][j], N, wmma::mem_row_major);
}

// ---------------------------------------------------------------------------
// Neighborhood attention: 4 threads per query (512 threads, 128 queries/blk).
// ---------------------------------------------------------------------------
__global__ void __launch_bounds__(512) na1d_kernel(
    const float* __restrict__ qkv, float* __restrict__ outp)
{
    extern __shared__ float shf[];
    float* Ks = shf;                  // [160][KVP]
    float* Vs = shf + 160 * KVP;

    const int tid = threadIdx.x;
    const int b  = blockIdx.z;
    const int h  = blockIdx.y;
    const int q0 = blockIdx.x * BQ;

    const int smin = min(max(q0 - (KSZ / 2), 0), LSEQ - KSZ);
    const int smax = min(max(q0 + BQ - 1 - (KSZ / 2), 0), LSEQ - KSZ);
    const int nk   = smax - smin + KSZ;   // <= 160

    const float* kb = qkv + ((size_t)(b * LSEQ + smin)) * QKVDIM + DIMSZ + h * HD;
    for (int idx = tid; idx < nk * 16; idx += 512) {
        int j = idx >> 4;
        int s = (idx & 15) * 4;
        *(float4*)(Ks + j * KVP + s) = *(const float4*)(kb + (size_t)j * QKVDIM + s);
        *(float4*)(Vs + j * KVP + s) = *(const float4*)(kb + (size_t)j * QKVDIM + DIMSZ + s);
    }
    __syncthreads();

    const int l  = q0 + (tid >> 2);
    const int dp = (tid & 3) * 16;
    const int st  = min(max(l - (KSZ / 2), 0), LSEQ - KSZ);
    const int ks0 = st - smin;

    const float* qp = qkv + ((size_t)(b * LSEQ + l)) * QKVDIM + h * HD + dp;
    float qv[16];
#pragma unroll
    for (int s = 0; s < 16; s += 4) {
        float4 v = *(const float4*)(qp + s);
        qv[s] = v.x * 0.125f; qv[s+1] = v.y * 0.125f;
        qv[s+2] = v.z * 0.125f; qv[s+3] = v.w * 0.125f;
    }

    float sc[KSZ];
    float mx = -1e30f;
#pragma unroll
    for (int j = 0; j < KSZ; j++) {
        const float* kr = Ks + (ks0 + j) * KVP + dp;
        float p = 0.0f;
#pragma unroll
        for (int s = 0; s < 16; s += 4) {
            float4 v = *(const float4*)(kr + s);
            p = fmaf(qv[s], v.x, p);   p = fmaf(qv[s+1], v.y, p);
            p = fmaf(qv[s+2], v.z, p); p = fmaf(qv[s+3], v.w, p);
        }
        p += __shfl_xor_sync(0xFFFFFFFF, p, 1);
        p += __shfl_xor_sync(0xFFFFFFFF, p, 2);
        sc[j] = p;
        mx = fmaxf(mx, p);
    }

    float sum = 0.0f;
#pragma unroll
    for (int j = 0; j < KSZ; j++) {
        float p = __expf(sc[j] - mx);
        sc[j] = p;
        sum += p;
    }
    const float inv = 1.0f / sum;

    float o[16];
#pragma unroll
    for (int s = 0; s < 16; s++) o[s] = 0.0f;
#pragma unroll
    for (int j = 0; j < KSZ; j++) {
        const float p = sc[j];
        const float* vr = Vs + (ks0 + j) * KVP + dp;
#pragma unroll
        for (int s = 0; s < 16; s += 4) {
            float4 v = *(const float4*)(vr + s);
            o[s]   = fmaf(p, v.x, o[s]);   o[s+1] = fmaf(p, v.y, o[s+1]);
            o[s+2] = fmaf(p, v.z, o[s+2]); o[s+3] = fmaf(p, v.w, o[s+3]);
        }
    }

    float* op = outp + ((size_t)(b * LSEQ + l)) * DIMSZ + h * HD + dp;
#pragma unroll
    for (int s = 0; s < 16; s += 4) {
        float4 v;
        v.x = o[s] * inv; v.y = o[s+1] * inv;
        v.z = o[s+2] * inv; v.w = o[s+3] * inv;
        *(float4*)(op + s) = v;
    }
}

// ---------------------------------------------------------------------------
// Launch
// ---------------------------------------------------------------------------
extern "C" void kernel_launch(void* const* d_in, const int* in_sizes, int n_in,
                              void* d_out, int out_size)
{
    const float* x      = (const float*)d_in[0];
    const float* w_qkv  = (const float*)d_in[1];
    const float* b_qkv  = (const float*)d_in[2];
    const float* w_proj = (const float*)d_in[3];
    const float* b_proj = (const float*)d_in[4];
    float*       out    = (float*)d_out;

    float *qkv, *att;
    __nv_bfloat16 *a2, *wq2, *wp2;
    cudaGetSymbolAddress((void**)&qkv, g_qkv);
    cudaGetSymbolAddress((void**)&att, g_att);
    cudaGetSymbolAddress((void**)&a2,  g_a2);
    cudaGetSymbolAddress((void**)&wq2, g_wq2);
    cudaGetSymbolAddress((void**)&wp2, g_wp2);

    cudaFuncSetAttribute(na1d_kernel,
                         cudaFuncAttributeMaxDynamicSharedMemorySize, ATT_SMEM);
    cudaFuncSetAttribute(gemm_wmma,
                         cudaFuncAttributeMaxDynamicSharedMemorySize, SM_TOTAL);

    // Compact [hi|lo] splits
    split_bf16<<<(MROWS * KIN / 4) / 256, 256>>>((const float4*)x, a2,
                                                 MROWS * KIN / 4);
    split_bf16<<<(QKVDIM * KIN / 4) / 256, 256>>>((const float4*)w_qkv, wq2,
                                                  QKVDIM * KIN / 4);
    split_bf16<<<(DIMSZ * KIN / 4) / 256, 256>>>((const float4*)w_proj, wp2,
                                                 DIMSZ * KIN / 4);

    // 1) QKV projection
    dim3 g1(QKVDIM / NT, MROWS / MT);
    gemm_wmma<<<g1, 512, SM_TOTAL>>>(a2, wq2, b_qkv, qkv, QKVDIM);

    // 2) Neighborhood attention
    dim3 g2(LSEQ / BQ, NHEADS, BATCH);
    na1d_kernel<<<g2, 512, ATT_SMEM>>>(qkv, att);

    // 3) Split attention output, then output projection
    split_bf16<<<(MROWS * KIN / 4) / 256, 256>>>((const float4*)att, a2,
                                                 MROWS * KIN / 4);
    dim3 g3(DIMSZ / NT, MROWS / MT);
    gemm_wmma<<<g3, 512, SM_TOTAL>>>(a2, wp2, b_proj, out, DIMSZ);
}